// round 2
// baseline (speedup 1.0000x reference)
#include <cuda_runtime.h>

#define NN   1024   // nodes
#define TT   36     // time steps
#define EMB  64     // embed dim
#define NH   4      // heads
#define HD   16     // head dim
#define SCALE 0.125f  // 1/sqrt(EMBED=64)

// Intermediate context [N, T, EMB] (attention output before final projection).
// __device__ global scratch — no runtime allocation.
__device__ float g_ctx[(size_t)NN * TT * EMB];

// ---------------------------------------------------------------------------
// Kernel 1: fused QKV projection + node-attention (flash-style online softmax)
// One CTA per (t, h). K,V slices projected into SMEM (1024 x 16 each).
// Each thread handles 4 query rows sequentially.
// ---------------------------------------------------------------------------
__global__ __launch_bounds__(256, 1)
void attn_kernel(const float* __restrict__ values,
                 const float* __restrict__ keys,
                 const float* __restrict__ query,
                 const float* __restrict__ Wv,
                 const float* __restrict__ Wk,
                 const float* __restrict__ Wq)
{
    extern __shared__ float smem[];
    float* Ks = smem;              // [NN][HD]
    float* Vs = smem + NN * HD;    // [NN][HD]
    __shared__ float Wks[HD * HD];
    __shared__ float Wvs[HD * HD];
    __shared__ float Wqs[HD * HD];

    const int tid = threadIdx.x;
    const int t   = blockIdx.x / NH;
    const int h   = blockIdx.x % NH;

    if (tid < HD * HD) {
        Wks[tid] = Wk[tid];
        Wvs[tid] = Wv[tid];
        Wqs[tid] = Wq[tid];
    }
    __syncthreads();

    // ---- Project K and V for all 1024 nodes into SMEM ----
    #pragma unroll
    for (int r = 0; r < 4; r++) {
        const int n = tid + r * 256;
        const size_t base = ((size_t)n * TT + t) * EMB + h * HD;

        float kin[HD], vin[HD];
        #pragma unroll
        for (int i = 0; i < 4; i++) {
            float4 a = *(const float4*)(keys + base + i * 4);
            kin[i*4+0] = a.x; kin[i*4+1] = a.y; kin[i*4+2] = a.z; kin[i*4+3] = a.w;
            float4 b = *(const float4*)(values + base + i * 4);
            vin[i*4+0] = b.x; vin[i*4+1] = b.y; vin[i*4+2] = b.z; vin[i*4+3] = b.w;
        }
        #pragma unroll
        for (int e = 0; e < HD; e++) {
            float sk = 0.f, sv = 0.f;
            #pragma unroll
            for (int d = 0; d < HD; d++) {
                sk = fmaf(kin[d], Wks[e * HD + d], sk);
                sv = fmaf(vin[d], Wvs[e * HD + d], sv);
            }
            Ks[n * HD + e] = sk;
            Vs[n * HD + e] = sv;
        }
    }
    __syncthreads();

    // ---- Flash attention per query row (4 rows per thread, sequential) ----
    for (int r = 0; r < 4; r++) {
        const int nq = tid + r * 256;
        const size_t qbase = ((size_t)nq * TT + t) * EMB + h * HD;

        float qin[HD];
        #pragma unroll
        for (int i = 0; i < 4; i++) {
            float4 a = *(const float4*)(query + qbase + i * 4);
            qin[i*4+0] = a.x; qin[i*4+1] = a.y; qin[i*4+2] = a.z; qin[i*4+3] = a.w;
        }
        float q[HD];
        #pragma unroll
        for (int e = 0; e < HD; e++) {
            float s = 0.f;
            #pragma unroll
            for (int d = 0; d < HD; d++)
                s = fmaf(qin[d], Wqs[e * HD + d], s);
            q[e] = s * SCALE;  // fold softmax scale into q
        }

        float m = -1e30f, l = 0.f;
        float acc[HD];
        #pragma unroll
        for (int d = 0; d < HD; d++) acc[d] = 0.f;

        for (int j0 = 0; j0 < NN; j0 += 16) {
            float s[16];
            #pragma unroll
            for (int c = 0; c < 16; c++) {
                const float4* kr = (const float4*)(Ks + (j0 + c) * HD);
                float4 k0 = kr[0], k1 = kr[1], k2 = kr[2], k3 = kr[3];
                float a0 = q[0]*k0.x + q[1]*k0.y + q[2]*k0.z + q[3]*k0.w;
                float a1 = q[4]*k1.x + q[5]*k1.y + q[6]*k1.z + q[7]*k1.w;
                float a2 = q[8]*k2.x + q[9]*k2.y + q[10]*k2.z + q[11]*k2.w;
                float a3 = q[12]*k3.x + q[13]*k3.y + q[14]*k3.z + q[15]*k3.w;
                s[c] = (a0 + a1) + (a2 + a3);
            }
            float cm = s[0];
            #pragma unroll
            for (int c = 1; c < 16; c++) cm = fmaxf(cm, s[c]);
            const float nm = fmaxf(m, cm);
            const float corr = __expf(m - nm);
            l *= corr;
            #pragma unroll
            for (int d = 0; d < HD; d++) acc[d] *= corr;

            #pragma unroll
            for (int c = 0; c < 16; c++) {
                const float p = __expf(s[c] - nm);
                l += p;
                const float4* vr = (const float4*)(Vs + (j0 + c) * HD);
                float4 v0 = vr[0], v1 = vr[1], v2 = vr[2], v3 = vr[3];
                acc[0]  = fmaf(p, v0.x, acc[0]);
                acc[1]  = fmaf(p, v0.y, acc[1]);
                acc[2]  = fmaf(p, v0.z, acc[2]);
                acc[3]  = fmaf(p, v0.w, acc[3]);
                acc[4]  = fmaf(p, v1.x, acc[4]);
                acc[5]  = fmaf(p, v1.y, acc[5]);
                acc[6]  = fmaf(p, v1.z, acc[6]);
                acc[7]  = fmaf(p, v1.w, acc[7]);
                acc[8]  = fmaf(p, v2.x, acc[8]);
                acc[9]  = fmaf(p, v2.y, acc[9]);
                acc[10] = fmaf(p, v2.z, acc[10]);
                acc[11] = fmaf(p, v2.w, acc[11]);
                acc[12] = fmaf(p, v3.x, acc[12]);
                acc[13] = fmaf(p, v3.y, acc[13]);
                acc[14] = fmaf(p, v3.z, acc[14]);
                acc[15] = fmaf(p, v3.w, acc[15]);
            }
            m = nm;
        }

        const float inv = 1.f / l;
        float* op = g_ctx + qbase;
        #pragma unroll
        for (int i = 0; i < 4; i++) {
            float4 o;
            o.x = acc[i*4+0] * inv;
            o.y = acc[i*4+1] * inv;
            o.z = acc[i*4+2] * inv;
            o.w = acc[i*4+3] * inv;
            *(float4*)(op + i * 4) = o;
        }
    }
}

// ---------------------------------------------------------------------------
// Kernel 2: output projection  out[row,:] = ctx[row,:] @ Wo^T + bo
// One row per thread; Wo/bo staged in SMEM (warp-uniform broadcast reads).
// ---------------------------------------------------------------------------
__global__ __launch_bounds__(256, 1)
void oproj_kernel(const float* __restrict__ Wo,
                  const float* __restrict__ bo,
                  float* __restrict__ out)
{
    __shared__ float Wos[EMB * EMB];
    __shared__ float bos[EMB];
    const int tid = threadIdx.x;
    for (int i = tid; i < EMB * EMB; i += 256) Wos[i] = Wo[i];
    if (tid < EMB) bos[tid] = bo[tid];
    __syncthreads();

    const size_t row = (size_t)blockIdx.x * 256 + tid;  // 36864 rows total
    const float* xp = g_ctx + row * EMB;

    float x[EMB];
    #pragma unroll
    for (int i = 0; i < 16; i++) {
        float4 a = *(const float4*)(xp + i * 4);
        x[i*4+0] = a.x; x[i*4+1] = a.y; x[i*4+2] = a.z; x[i*4+3] = a.w;
    }

    float* op = out + row * EMB;
    for (int e0 = 0; e0 < EMB; e0 += 8) {   // runtime loop: keeps code size in I$
        float res[8];
        #pragma unroll
        for (int k = 0; k < 8; k++) res[k] = bos[e0 + k];
        #pragma unroll
        for (int d = 0; d < EMB; d++) {     // fully unrolled: x[d] stays in regs
            const float xd = x[d];
            #pragma unroll
            for (int k = 0; k < 8; k++)
                res[k] = fmaf(xd, Wos[(e0 + k) * EMB + d], res[k]);
        }
        float4 o0, o1;
        o0.x = res[0]; o0.y = res[1]; o0.z = res[2]; o0.w = res[3];
        o1.x = res[4]; o1.y = res[5]; o1.z = res[6]; o1.w = res[7];
        *(float4*)(op + e0)     = o0;
        *(float4*)(op + e0 + 4) = o1;
    }
}

// ---------------------------------------------------------------------------
extern "C" void kernel_launch(void* const* d_in, const int* in_sizes, int n_in,
                              void* d_out, int out_size)
{
    const float* values = (const float*)d_in[0];
    const float* keys   = (const float*)d_in[1];
    const float* query  = (const float*)d_in[2];
    const float* Wv     = (const float*)d_in[3];
    const float* Wk     = (const float*)d_in[4];
    const float* Wq     = (const float*)d_in[5];
    const float* Wo     = (const float*)d_in[6];
    const float* bo     = (const float*)d_in[7];
    float* out = (float*)d_out;

    const int smem_bytes = 2 * NN * HD * (int)sizeof(float);  // 131072
    cudaFuncSetAttribute(attn_kernel,
                         cudaFuncAttributeMaxDynamicSharedMemorySize, smem_bytes);

    attn_kernel<<<TT * NH, 256, smem_bytes>>>(values, keys, query, Wv, Wk, Wq);
    oproj_kernel<<<(NN * TT) / 256, 256>>>(Wo, bo, out);
}

// round 3
// speedup vs baseline: 1.8135x; 1.8135x over previous
#include <cuda_runtime.h>

#define NN   1024   // nodes
#define TT   36     // time steps
#define EMB  64     // embed dim
#define NH   4      // heads
#define HD   16     // head dim

typedef unsigned long long ull;

// packed f32x2 ops (sm_100+/sm_103a): 2 MACs per fma-pipe slot
#define FMA2(d,a,b,c) asm("fma.rn.f32x2 %0, %1, %2, %3;" : "=l"(d) : "l"(a), "l"(b), "l"(c))
#define MUL2(d,a,b)   asm("mul.rn.f32x2 %0, %1, %2;"     : "=l"(d) : "l"(a), "l"(b))
#define ADD2(d,a,b)   asm("add.rn.f32x2 %0, %1, %2;"     : "=l"(d) : "l"(a), "l"(b))
#define PACK2(d,lo,hi)   asm("mov.b64 %0, {%1, %2};" : "=l"(d) : "f"(lo), "f"(hi))
#define UNPACK2(lo,hi,s) asm("mov.b64 {%0, %1}, %2;" : "=f"(lo), "=f"(hi) : "l"(s))
#define EX2(d,a) asm("ex2.approx.ftz.f32 %0, %1;" : "=f"(d) : "f"(a))

// softmax scale folded with log2(e): energy * 0.125, exp -> 2^x
#define QSCALE 0.18033688f   // 0.125 * 1.4426950408889634

// Intermediate context [N, T, EMB] — __device__ global scratch (no allocation).
__device__ float g_ctx[(size_t)NN * TT * EMB];

// ---------------------------------------------------------------------------
// Kernel 1: fused QKV projection + node-attention, f32x2-packed.
// One CTA per (t, h). Kt stored TRANSPOSED [HD][NN] so key-pairs land in the
// two f32x2 lanes; Vs row-major [NN][HD] for packed-over-d accumulation.
// Each thread: 2 passes x 2 query rows.
// ---------------------------------------------------------------------------
__global__ __launch_bounds__(256, 1)
void attn_kernel(const float* __restrict__ values,
                 const float* __restrict__ keys,
                 const float* __restrict__ query,
                 const float* __restrict__ Wv,
                 const float* __restrict__ Wk,
                 const float* __restrict__ Wq)
{
    extern __shared__ float smem[];
    float* Kt = smem;              // [HD][NN] transposed
    float* Vs = smem + HD * NN;    // [NN][HD]
    __shared__ float Wks[HD * HD];
    __shared__ float Wvs[HD * HD];
    __shared__ float Wqs[HD * HD];

    const int tid = threadIdx.x;
    const int t   = blockIdx.x / NH;
    const int h   = blockIdx.x % NH;

    Wks[tid] = Wk[tid];
    Wvs[tid] = Wv[tid];
    Wqs[tid] = Wq[tid];
    __syncthreads();

    // ---- Project K (transposed store) and V for all 1024 nodes ----
    #pragma unroll
    for (int r = 0; r < 4; r++) {
        const int n = tid + r * 256;
        const size_t base = ((size_t)n * TT + t) * EMB + h * HD;

        float kin[HD], vin[HD];
        #pragma unroll
        for (int i = 0; i < 4; i++) {
            float4 a = *(const float4*)(keys + base + i * 4);
            kin[i*4+0] = a.x; kin[i*4+1] = a.y; kin[i*4+2] = a.z; kin[i*4+3] = a.w;
            float4 b = *(const float4*)(values + base + i * 4);
            vin[i*4+0] = b.x; vin[i*4+1] = b.y; vin[i*4+2] = b.z; vin[i*4+3] = b.w;
        }
        float vout[HD];
        #pragma unroll
        for (int e = 0; e < HD; e++) {
            float sk = 0.f, sv = 0.f;
            #pragma unroll
            for (int d = 0; d < HD; d++) {
                sk = fmaf(kin[d], Wks[e * HD + d], sk);
                sv = fmaf(vin[d], Wvs[e * HD + d], sv);
            }
            Kt[e * NN + n] = sk;   // transposed
            vout[e] = sv;
        }
        #pragma unroll
        for (int i = 0; i < 4; i++) {
            float4 o;
            o.x = vout[i*4+0]; o.y = vout[i*4+1];
            o.z = vout[i*4+2]; o.w = vout[i*4+3];
            *(float4*)(Vs + n * HD + i * 4) = o;
        }
    }
    __syncthreads();

    // ---- Flash attention: 2 passes x 2 rows per thread ----
    for (int pass = 0; pass < 2; pass++) {
        ull  q2[2][HD];      // q broadcast-packed (q,q), pre-scaled to log2 domain
        ull  acc[2][8];      // output accum, packed over d
        float m[2], l[2];

        #pragma unroll
        for (int r = 0; r < 2; r++) {
            const int nq = tid + (pass * 2 + r) * 256;
            const size_t qb = ((size_t)nq * TT + t) * EMB + h * HD;
            float qin[HD];
            #pragma unroll
            for (int i = 0; i < 4; i++) {
                float4 a = *(const float4*)(query + qb + i * 4);
                qin[i*4+0] = a.x; qin[i*4+1] = a.y; qin[i*4+2] = a.z; qin[i*4+3] = a.w;
            }
            #pragma unroll
            for (int e = 0; e < HD; e++) {
                float s = 0.f;
                #pragma unroll
                for (int d = 0; d < HD; d++)
                    s = fmaf(qin[d], Wqs[e * HD + d], s);
                s *= QSCALE;
                PACK2(q2[r][e], s, s);
            }
            m[r] = -1e30f; l[r] = 0.f;
            #pragma unroll
            for (int i = 0; i < 8; i++) acc[r][i] = 0ull;
        }

        for (int j0 = 0; j0 < NN; j0 += 16) {
            // ---- QK^T: 8 key-pairs, both rows, packed lanes = adjacent keys
            ull s2[2][8];
            #pragma unroll
            for (int pk = 0; pk < 8; pk++) {
                ull a0 = 0ull, a1 = 0ull;
                #pragma unroll
                for (int d = 0; d < HD; d++) {
                    ull k2 = *(const ull*)(Kt + d * NN + j0 + pk * 2);
                    FMA2(a0, q2[0][d], k2, a0);
                    FMA2(a1, q2[1][d], k2, a1);
                }
                s2[0][pk] = a0; s2[1][pk] = a1;
            }

            // ---- per-row online softmax + PV
            #pragma unroll
            for (int r = 0; r < 2; r++) {
                float sv[16];
                #pragma unroll
                for (int pk = 0; pk < 8; pk++)
                    UNPACK2(sv[2*pk], sv[2*pk+1], s2[r][pk]);

                float cm = sv[0];
                #pragma unroll
                for (int c = 1; c < 16; c++) cm = fmaxf(cm, sv[c]);
                const float nm = fmaxf(m[r], cm);
                float corr; EX2(corr, m[r] - nm);
                m[r] = nm;
                l[r] *= corr;
                ull corr2; PACK2(corr2, corr, corr);
                #pragma unroll
                for (int i = 0; i < 8; i++) MUL2(acc[r][i], acc[r][i], corr2);

                #pragma unroll
                for (int c = 0; c < 16; c++) {
                    float p; EX2(p, sv[c] - nm);
                    l[r] += p;
                    ull pp; PACK2(pp, p, p);
                    const float4* vp = (const float4*)(Vs + (j0 + c) * HD);
                    float4 v0 = vp[0], v1 = vp[1], v2 = vp[2], v3 = vp[3];
                    ull w0, w1, w2, w3, w4, w5, w6, w7;
                    PACK2(w0, v0.x, v0.y); PACK2(w1, v0.z, v0.w);
                    PACK2(w2, v1.x, v1.y); PACK2(w3, v1.z, v1.w);
                    PACK2(w4, v2.x, v2.y); PACK2(w5, v2.z, v2.w);
                    PACK2(w6, v3.x, v3.y); PACK2(w7, v3.z, v3.w);
                    FMA2(acc[r][0], pp, w0, acc[r][0]);
                    FMA2(acc[r][1], pp, w1, acc[r][1]);
                    FMA2(acc[r][2], pp, w2, acc[r][2]);
                    FMA2(acc[r][3], pp, w3, acc[r][3]);
                    FMA2(acc[r][4], pp, w4, acc[r][4]);
                    FMA2(acc[r][5], pp, w5, acc[r][5]);
                    FMA2(acc[r][6], pp, w6, acc[r][6]);
                    FMA2(acc[r][7], pp, w7, acc[r][7]);
                }
            }
        }

        // ---- epilogue: normalize + store context
        #pragma unroll
        for (int r = 0; r < 2; r++) {
            const float inv = 1.f / l[r];
            ull inv2; PACK2(inv2, inv, inv);
            const int nq = tid + (pass * 2 + r) * 256;
            float* op = g_ctx + ((size_t)nq * TT + t) * EMB + h * HD;
            #pragma unroll
            for (int i = 0; i < 8; i++) {
                ull o; MUL2(o, acc[r][i], inv2);
                *(ull*)(op + i * 2) = o;
            }
        }
    }
}

// ---------------------------------------------------------------------------
// Kernel 2: output projection, f32x2-packed.  out[row,:] = ctx[row,:]@Wo^T + bo
// ---------------------------------------------------------------------------
__global__ __launch_bounds__(256, 1)
void oproj_kernel(const float* __restrict__ Wo,
                  const float* __restrict__ bo,
                  float* __restrict__ out)
{
    __shared__ float Wos[EMB * EMB];
    __shared__ float bos[EMB];
    const int tid = threadIdx.x;
    for (int i = tid; i < EMB * EMB; i += 256) Wos[i] = Wo[i];
    if (tid < EMB) bos[tid] = bo[tid];
    __syncthreads();

    const size_t row = (size_t)blockIdx.x * 256 + tid;
    const float* xp = g_ctx + row * EMB;

    ull x2[32];
    #pragma unroll
    for (int i = 0; i < 16; i++) {
        float4 a = *(const float4*)(xp + i * 4);
        PACK2(x2[2*i+0], a.x, a.y);
        PACK2(x2[2*i+1], a.z, a.w);
    }

    float* op = out + row * EMB;
    #pragma unroll 2
    for (int e0 = 0; e0 < EMB; e0 += 4) {
        float res[4];
        #pragma unroll
        for (int k = 0; k < 4; k++) {
            ull a = 0ull;
            const float* wr = Wos + (e0 + k) * EMB;
            #pragma unroll
            for (int i = 0; i < 16; i++) {
                float4 w = *(const float4*)(wr + i * 4);
                ull w0, w1;
                PACK2(w0, w.x, w.y); PACK2(w1, w.z, w.w);
                FMA2(a, x2[2*i+0], w0, a);
                FMA2(a, x2[2*i+1], w1, a);
            }
            float lo, hi; UNPACK2(lo, hi, a);
            res[k] = bos[e0 + k] + lo + hi;
        }
        float4 o;
        o.x = res[0]; o.y = res[1]; o.z = res[2]; o.w = res[3];
        *(float4*)(op + e0) = o;
    }
}

// ---------------------------------------------------------------------------
extern "C" void kernel_launch(void* const* d_in, const int* in_sizes, int n_in,
                              void* d_out, int out_size)
{
    const float* values = (const float*)d_in[0];
    const float* keys   = (const float*)d_in[1];
    const float* query  = (const float*)d_in[2];
    const float* Wv     = (const float*)d_in[3];
    const float* Wk     = (const float*)d_in[4];
    const float* Wq     = (const float*)d_in[5];
    const float* Wo     = (const float*)d_in[6];
    const float* bo     = (const float*)d_in[7];
    float* out = (float*)d_out;

    const int smem_bytes = 2 * NN * HD * (int)sizeof(float);  // 131072
    cudaFuncSetAttribute(attn_kernel,
                         cudaFuncAttributeMaxDynamicSharedMemorySize, smem_bytes);

    attn_kernel<<<TT * NH, 256, smem_bytes>>>(values, keys, query, Wv, Wk, Wq);
    oproj_kernel<<<(NN * TT) / 256, 256>>>(Wo, bo, out);
}